// round 4
// baseline (speedup 1.0000x reference)
#include <cuda_runtime.h>

// S4D kernel: K[h,l] = 2 * Re( sum_n Cmod[h,n] * exp(dtA[h,n] * l) ),
// H=1024, N=64, L=2048.
//
// Per (h,n): r_l = Re(Cmod * exp(dtA*l)) at l-stride 32 obeys
//   r_{k+2} = p*r_{k+1} + q*r_k,  w = exp(dtA*32), p = 2Re(w), q = -|w|^2
// (|roots| < 1: stable). Grid = 2*H: block (h, half) computes k-range
// [half*32, half*32+32) of the 64 k-steps. 128 thr / 4 warps per block,
// lane owns l = lane + 32k. Warp w owns n in [16w, 16w+16) -> 8 packed
// f32x2 states per thread. No barriers in the main loop; per-iteration
// partials land in a 16KB shared buffer, one final reduction pass.

#define N_     64
#define WARPS  4
#define NPW    (N_ / WARPS)    // 16 n per warp
#define NPAIR  (NPW / 2)       // 8 packed pairs per thread
#define KT_B   32              // k-steps per block
#define ITERS  (KT_B / 2)      // 16 iterations (2 k per iter)

typedef unsigned long long u64;

__device__ __forceinline__ u64 pack2(float lo, float hi) {
    u64 r; asm("mov.b64 %0, {%1,%2};" : "=l"(r) : "f"(lo), "f"(hi)); return r;
}
__device__ __forceinline__ void unpack2(u64 v, float& lo, float& hi) {
    asm("mov.b64 {%0,%1}, %2;" : "=f"(lo), "=f"(hi) : "l"(v));
}
__device__ __forceinline__ u64 fma2(u64 a, u64 b, u64 c) {
    u64 d; asm("fma.rn.f32x2 %0,%1,%2,%3;" : "=l"(d) : "l"(a), "l"(b), "l"(c)); return d;
}
__device__ __forceinline__ u64 mul2(u64 a, u64 b) {
    u64 d; asm("mul.rn.f32x2 %0,%1,%2;" : "=l"(d) : "l"(a), "l"(b)); return d;
}
__device__ __forceinline__ u64 add2(u64 a, u64 b) {
    u64 d; asm("add.rn.f32x2 %0,%1,%2;" : "=l"(d) : "l"(a), "l"(b)); return d;
}

__global__ __launch_bounds__(128)
void s4d_fused(const float* __restrict__ log_dt,
               const float* __restrict__ C,
               const float* __restrict__ A,
               float* __restrict__ out, int L)
{
    __shared__ float2 s_dta[N_], s_cm[N_], s_w32[N_], s_pq[N_];
    __shared__ float2 s_wP[N_];                 // exp(dtA * 1024)
    __shared__ float2 s_part[ITERS][WARPS][32]; // per-iteration partials (16KB)

    const int h    = blockIdx.x >> 1;
    const int half = blockIdx.x & 1;
    const int tid  = threadIdx.x;
    const int wid  = tid >> 5;
    const int lane = tid & 31;

    // ---- per-n parameter precompute (threads 0..63, one n each) ----
    if (tid < N_) {
        int n = tid;
        float dt  = expf(log_dt[h]);
        float ar  = A[2 * n], ai = A[2 * n + 1];
        float dre = dt * ar, dim = dt * ai;

        float e1 = expf(dre); float s1, c1; sincosf(dim, &s1, &c1);
        float w1r = e1 * c1, w1i = e1 * s1;

        float inv = 1.0f / (ar * ar + ai * ai);
        float nr = w1r - 1.0f, ni = w1i;
        float qdr = (nr * ar + ni * ai) * inv;
        float qdi = (ni * ar - nr * ai) * inv;

        float cr = C[2 * (h * N_ + n)], ci = C[2 * (h * N_ + n) + 1];
        float cmr = 2.0f * (cr * qdr - ci * qdi);
        float cmi = 2.0f * (cr * qdi + ci * qdr);

        float e32 = expf(32.0f * dre); float s32, c32; sincosf(32.0f * dim, &s32, &c32);
        float wr = e32 * c32, wi = e32 * s32;

        // w^1024 = (w^32)^32 via 5 squarings (graceful underflow to 0)
        float pr = wr, pi = wi;
#pragma unroll
        for (int sq = 0; sq < 5; sq++) {
            float tr = pr * pr - pi * pi;
            float ti = 2.0f * pr * pi;
            pr = tr; pi = ti;
        }

        s_dta[n] = make_float2(dre, dim);
        s_cm [n] = make_float2(cmr, cmi);
        s_w32[n] = make_float2(wr, wi);
        s_wP [n] = make_float2(pr, pi);
        s_pq [n] = make_float2(2.0f * wr, -(wr * wr + wi * wi));
    }
    __syncthreads();

    // ---- per-thread state init at l0 = lane (+1024 if half==1) ----
    const float lf = (float)lane;
    const int   n0 = wid * NPW;

    u64 ra[NPAIR], rb[NPAIR], p2[NPAIR], q2[NPAIR];
#pragma unroll
    for (int j = 0; j < NPAIR; j++) {
        float z0[2], z1[2];
#pragma unroll
        for (int t = 0; t < 2; t++) {
            int n = n0 + 2 * j + t;
            float2 d = s_dta[n];
            float ex = expf(d.x * lf);
            float s, c; sincosf(d.y * lf, &s, &c);
            float er = ex * c, ei = ex * s;
            float2 cm = s_cm[n];
            float zr = cm.x * er - cm.y * ei;       // z = cm * exp(dtA*lane)
            float zi = cm.x * ei + cm.y * er;
            if (half) {                              // advance by 1024 steps
                float2 wp = s_wP[n];
                float tr = zr * wp.x - zi * wp.y;
                float ti = zr * wp.y + zi * wp.x;
                zr = tr; zi = ti;
            }
            float2 w = s_w32[n];
            z0[t] = zr;
            z1[t] = zr * w.x - zi * w.y;             // Re(z * w32)
        }
        ra[j] = pack2(z0[0], z0[1]);
        rb[j] = pack2(z1[0], z1[1]);
        float2 pqa = s_pq[n0 + 2 * j];
        float2 pqb = s_pq[n0 + 2 * j + 1];
        p2[j] = pack2(pqa.x, pqb.x);
        q2[j] = pack2(pqa.y, pqb.y);
    }

    // ---- main loop: no barriers; partials to shared ----
    float2* s_row = &s_part[0][wid][lane];
#pragma unroll 2
    for (int it = 0; it < ITERS; it++) {
        u64 a0 = 0ull, a1 = 0ull, b0 = 0ull, b1 = 0ull;
#pragma unroll
        for (int j = 0; j < NPAIR; j++) {
            if (j & 1) {
                a1 = add2(a1, ra[j]);
                ra[j] = fma2(p2[j], rb[j], mul2(q2[j], ra[j]));
                b1 = add2(b1, rb[j]);
                rb[j] = fma2(p2[j], ra[j], mul2(q2[j], rb[j]));
            } else {
                a0 = add2(a0, ra[j]);
                ra[j] = fma2(p2[j], rb[j], mul2(q2[j], ra[j]));
                b0 = add2(b0, rb[j]);
                rb[j] = fma2(p2[j], ra[j], mul2(q2[j], rb[j]));
            }
        }
        u64 aa = add2(a0, a1), bb = add2(b0, b1);
        float al, ah, bl, bh;
        unpack2(aa, al, ah); unpack2(bb, bl, bh);
        s_row[(size_t)it * (WARPS * 32)] = make_float2(al + ah, bl + bh);
    }
    __syncthreads();

    // ---- final cross-warp reduction: warp w handles k_local = w + 4i ----
    float* orow = out + (size_t)h * L + (size_t)half * KT_B * 32;
#pragma unroll
    for (int i = 0; i < ITERS / 2; i++) {
        int k  = wid + 4 * i;
        int it = k >> 1;
        float2 v0 = s_part[it][0][lane];
        float2 v1 = s_part[it][1][lane];
        float2 v2 = s_part[it][2][lane];
        float2 v3 = s_part[it][3][lane];
        float r = (wid & 1) ? ((v0.y + v1.y) + (v2.y + v3.y))
                            : ((v0.x + v1.x) + (v2.x + v3.x));
        orow[(size_t)k * 32 + lane] = r;
    }
}

extern "C" void kernel_launch(void* const* d_in, const int* in_sizes, int n_in,
                              void* d_out, int out_size)
{
    const float* log_dt = (const float*)d_in[0];
    const float* C      = (const float*)d_in[1];
    const float* A      = (const float*)d_in[2];
    // d_in[3] = input_length scalar; L derived from out_size.

    int H = in_sizes[0];          // 1024
    int L = out_size / H;         // 2048

    s4d_fused<<<H * 2, 128>>>(log_dt, C, A, (float*)d_out, L);
}

// round 5
// speedup vs baseline: 1.1986x; 1.1986x over previous
#include <cuda_runtime.h>

// S4D kernel: K[h,l] = 2 * Re( sum_n Cmod[h,n] * exp(dtA[h,n] * l) ),
// H=1024, N=64, L=2048.
//
// Per (h,n): r_l = Re(Cmod * exp(dtA*l)) at l-stride 32 obeys
//   r_{k+2} = p*r_{k+1} + q*r_k,  w = exp(dtA*32), p = 2Re(w), q = -|w|^2
// (|roots| < 1: stable). One block (256 thr, 8 warps) per h. Lane owns
// l = lane + 32k. Warp w owns n in [8w, 8w+8) -> 4 packed f32x2 states per
// thread (32 state regs -> <=64 total, 4 blocks/SM, 50% occ). Main loop has
// no per-iteration barriers; per-iter packed partials (one STS.128) land in
// a 32KB buffer covering 8 iterations; 4 chunks with 2 barriers each.

#define N_     64
#define WARPS  8
#define NPW    (N_ / WARPS)    // 8 n per warp
#define NPAIR  (NPW / 2)       // 4 packed pairs per thread
#define CHUNK  8               // iterations per chunk (2 k each)
#define CHUNKS 4               // 32 iterations total = 64 k-steps

typedef unsigned long long u64;

__device__ __forceinline__ u64 pack2(float lo, float hi) {
    u64 r; asm("mov.b64 %0, {%1,%2};" : "=l"(r) : "f"(lo), "f"(hi)); return r;
}
__device__ __forceinline__ u64 fma2(u64 a, u64 b, u64 c) {
    u64 d; asm("fma.rn.f32x2 %0,%1,%2,%3;" : "=l"(d) : "l"(a), "l"(b), "l"(c)); return d;
}
__device__ __forceinline__ u64 mul2(u64 a, u64 b) {
    u64 d; asm("mul.rn.f32x2 %0,%1,%2;" : "=l"(d) : "l"(a), "l"(b)); return d;
}
__device__ __forceinline__ u64 add2(u64 a, u64 b) {
    u64 d; asm("add.rn.f32x2 %0,%1,%2;" : "=l"(d) : "l"(a), "l"(b)); return d;
}

__global__ __launch_bounds__(256, 4)
void s4d_fused(const float* __restrict__ log_dt,
               const float* __restrict__ C,
               const float* __restrict__ A,
               float* __restrict__ out, int L)
{
    __shared__ float2 s_dta[N_], s_cm[N_], s_w32[N_], s_pq[N_];
    // Packed partials: per (iter-in-chunk, warp, lane) one float4 = {aa.lo,
    // aa.hi, bb.lo, bb.hi}. 8*8*32*16B = 32KB.
    __shared__ float4 s_part[CHUNK * WARPS * 32];

    const int h    = blockIdx.x;
    const int tid  = threadIdx.x;
    const int wid  = tid >> 5;
    const int lane = tid & 31;

    // ---- per-n parameter precompute (threads 0..63, one n each) ----
    if (tid < N_) {
        int n = tid;
        float dt  = expf(log_dt[h]);
        float ar  = A[2 * n], ai = A[2 * n + 1];
        float dre = dt * ar, dim = dt * ai;

        float e1 = expf(dre); float s1, c1; sincosf(dim, &s1, &c1);
        float w1r = e1 * c1, w1i = e1 * s1;

        float inv = 1.0f / (ar * ar + ai * ai);
        float nr = w1r - 1.0f, ni = w1i;
        float qdr = (nr * ar + ni * ai) * inv;
        float qdi = (ni * ar - nr * ai) * inv;

        float cr = C[2 * (h * N_ + n)], ci = C[2 * (h * N_ + n) + 1];
        float cmr = 2.0f * (cr * qdr - ci * qdi);
        float cmi = 2.0f * (cr * qdi + ci * qdr);

        float e32 = expf(32.0f * dre); float s32, c32; sincosf(32.0f * dim, &s32, &c32);
        float wr = e32 * c32, wi = e32 * s32;

        s_dta[n] = make_float2(dre, dim);
        s_cm [n] = make_float2(cmr, cmi);
        s_w32[n] = make_float2(wr, wi);
        s_pq [n] = make_float2(2.0f * wr, -(wr * wr + wi * wi));
    }
    __syncthreads();

    // ---- per-thread state init: z0 = cm * exp(dtA * lane),
    //      ra = Re(z0), rb = Re(z0 * w32) ----
    const float lf = (float)lane;
    const int   n0 = wid * NPW;

    u64 ra[NPAIR], rb[NPAIR], p2[NPAIR], q2[NPAIR];
#pragma unroll
    for (int j = 0; j < NPAIR; j++) {
        float z0[2], z1[2];
#pragma unroll
        for (int t = 0; t < 2; t++) {
            int n = n0 + 2 * j + t;
            float2 d = s_dta[n];
            float ex = expf(d.x * lf);
            float s, c; sincosf(d.y * lf, &s, &c);
            float er = ex * c, ei = ex * s;
            float2 cm = s_cm[n];
            float zr = cm.x * er - cm.y * ei;
            float zi = cm.x * ei + cm.y * er;
            float2 w = s_w32[n];
            z0[t] = zr;
            z1[t] = zr * w.x - zi * w.y;
        }
        ra[j] = pack2(z0[0], z0[1]);
        rb[j] = pack2(z1[0], z1[1]);
        float2 pqa = s_pq[n0 + 2 * j];
        float2 pqb = s_pq[n0 + 2 * j + 1];
        p2[j] = pack2(pqa.x, pqb.x);
        q2[j] = pack2(pqa.y, pqb.y);
    }

    float* orow = out + (size_t)h * L;
    float4* s_slot = &s_part[wid * 32 + lane];

#pragma unroll 1
    for (int ch = 0; ch < CHUNKS; ch++) {
        if (ch) __syncthreads();           // buffer free after prior reduction

        // ---- 8 iterations (16 k-steps), no barriers, 1 STS.128 each ----
#pragma unroll
        for (int it = 0; it < CHUNK; it++) {
            u64 a0 = 0ull, a1 = 0ull, b0 = 0ull, b1 = 0ull;
#pragma unroll
            for (int j = 0; j < NPAIR; j++) {
                if (j & 1) {
                    a1 = add2(a1, ra[j]);
                    ra[j] = fma2(p2[j], rb[j], mul2(q2[j], ra[j]));
                    b1 = add2(b1, rb[j]);
                    rb[j] = fma2(p2[j], ra[j], mul2(q2[j], rb[j]));
                } else {
                    a0 = add2(a0, ra[j]);
                    ra[j] = fma2(p2[j], rb[j], mul2(q2[j], ra[j]));
                    b0 = add2(b0, rb[j]);
                    rb[j] = fma2(p2[j], ra[j], mul2(q2[j], rb[j]));
                }
            }
            ulonglong2 v;
            v.x = add2(a0, a1);            // aa: packed (lo,hi) partial for k
            v.y = add2(b0, b1);            // bb: partial for k+1
            *(ulonglong2*)&s_slot[it * (WARPS * 32)] = v;
        }
        __syncthreads();

        // ---- cross-warp reduction: warp w handles k_loc = w and w+8 ----
#pragma unroll
        for (int r = 0; r < 2; r++) {
            int k_loc = wid + 8 * r;       // 0..15 within chunk
            int it    = k_loc >> 1;
            int sel   = k_loc & 1;         // 0 -> aa, 1 -> bb
            const float2* base =
                (const float2*)&s_part[it * (WARPS * 32)];
            float sum = 0.0f;
#pragma unroll
            for (int w = 0; w < WARPS; w++) {
                float2 v = base[(w * 32 + lane) * 2 + sel];
                sum += v.x + v.y;
            }
            orow[(size_t)(ch * 16 + k_loc) * 32 + lane] = sum;
        }
    }
}

extern "C" void kernel_launch(void* const* d_in, const int* in_sizes, int n_in,
                              void* d_out, int out_size)
{
    const float* log_dt = (const float*)d_in[0];
    const float* C      = (const float*)d_in[1];
    const float* A      = (const float*)d_in[2];
    // d_in[3] = input_length scalar; L derived from out_size.

    int H = in_sizes[0];          // 1024
    int L = out_size / H;         // 2048

    s4d_fused<<<H, 256>>>(log_dt, C, A, (float*)d_out, L);
}

// round 6
// speedup vs baseline: 1.4270x; 1.1905x over previous
#include <cuda_runtime.h>

// S4D kernel: K[h,l] = 2 * Re( sum_n Cmod[h,n] * exp(dtA[h,n] * l) ),
// H=1024, N=64, L=2048.
//
// Modes n are merged in pairs: s_k = r_k[n] + r_k[n+1] satisfies an ORDER-4
// real recurrence s_{k+4} = c3 s_{k+3} + c2 s_{k+2} + c1 s_{k+1} + c0 s_k
// whose char poly is the product of the two mode quadratics (all |roots|<1:
// stable). This costs 2 fma-ops/(n,k) instead of 3.
//
// One block (128 thr, 4 warps) per h; lane owns l = lane + 32k, 64 k-steps.
// Warp w owns n in [16w,16w+16) = 8 merged streams = 4 packed f32x2
// stream-pairs. Main loop barrier-free; packed per-k partials (u64) land in
// a 32KB buffer per 32-k chunk; 2 chunks.

#define N_      64
#define WARPS   4
#define STREAMS 8              // merged streams per warp (2 n each)
#define SP      4              // packed stream-pairs per thread
#define CHUNK_K 32             // k-steps per chunk
#define CHUNKS  2

typedef unsigned long long u64;

__device__ __forceinline__ u64 pack2(float lo, float hi) {
    u64 r; asm("mov.b64 %0, {%1,%2};" : "=l"(r) : "f"(lo), "f"(hi)); return r;
}
__device__ __forceinline__ void unpack2(u64 v, float& lo, float& hi) {
    asm("mov.b64 {%0,%1}, %2;" : "=f"(lo), "=f"(hi) : "l"(v));
}
__device__ __forceinline__ u64 fma2(u64 a, u64 b, u64 c) {
    u64 d; asm("fma.rn.f32x2 %0,%1,%2,%3;" : "=l"(d) : "l"(a), "l"(b), "l"(c)); return d;
}
__device__ __forceinline__ u64 mul2(u64 a, u64 b) {
    u64 d; asm("mul.rn.f32x2 %0,%1,%2;" : "=l"(d) : "l"(a), "l"(b)); return d;
}
__device__ __forceinline__ u64 add2(u64 a, u64 b) {
    u64 d; asm("add.rn.f32x2 %0,%1,%2;" : "=l"(d) : "l"(a), "l"(b)); return d;
}

__global__ __launch_bounds__(128)
void s4d_fused(const float* __restrict__ log_dt,
               const float* __restrict__ C,
               const float* __restrict__ A,
               float* __restrict__ out, int L)
{
    __shared__ float2 s_dta[N_], s_cm[N_], s_w32[N_], s_pq[N_];
    __shared__ float4 s_c4[N_ / 2];                 // order-4 coeffs per merged pair
    __shared__ u64    s_part[CHUNK_K][WARPS][32];   // packed partials, 32KB

    const int h    = blockIdx.x;
    const int tid  = threadIdx.x;
    const int wid  = tid >> 5;
    const int lane = tid & 31;

    // ---- per-n parameter precompute (threads 0..63, one n each) ----
    if (tid < N_) {
        int n = tid;
        float dt  = expf(log_dt[h]);
        float ar  = A[2 * n], ai = A[2 * n + 1];
        float dre = dt * ar, dim = dt * ai;

        float e1 = expf(dre); float s1, c1; sincosf(dim, &s1, &c1);
        float w1r = e1 * c1, w1i = e1 * s1;

        float inv = 1.0f / (ar * ar + ai * ai);
        float nr = w1r - 1.0f, ni = w1i;
        float qdr = (nr * ar + ni * ai) * inv;
        float qdi = (ni * ar - nr * ai) * inv;

        float cr = C[2 * (h * N_ + n)], ci = C[2 * (h * N_ + n) + 1];
        float cmr = 2.0f * (cr * qdr - ci * qdi);
        float cmi = 2.0f * (cr * qdi + ci * qdr);

        float e32 = expf(32.0f * dre); float s32, c32; sincosf(32.0f * dim, &s32, &c32);
        float wr = e32 * c32, wi = e32 * s32;

        s_dta[n] = make_float2(dre, dim);
        s_cm [n] = make_float2(cmr, cmi);
        s_w32[n] = make_float2(wr, wi);
        s_pq [n] = make_float2(2.0f * wr, -(wr * wr + wi * wi));
    }
    __syncthreads();

    // ---- merged order-4 coefficients (threads 0..31, one merged pair each):
    //      (x^2 - p1 x - q1)(x^2 - p2 x - q2) ----
    if (tid < N_ / 2) {
        float2 a = s_pq[2 * tid], b = s_pq[2 * tid + 1];
        float c3 = a.x + b.x;
        float c2 = a.y + b.y - a.x * b.x;
        float c1 = -(a.x * b.y + b.x * a.y);
        float c0 = -a.y * b.y;
        s_c4[tid] = make_float4(c0, c1, c2, c3);
    }
    __syncthreads();

    // ---- per-thread state init: for each of my 16 n, z = cm*exp(dtA*lane),
    //      r_0..r_3 via complex stepping; merged s_k = r_k[n]+r_k[n+1] ----
    const float lf = (float)lane;
    const int   n0 = wid * 16;

    u64 S0[SP], S1[SP], S2[SP], S3[SP];
    u64 C0[SP], C1[SP], C2[SP], C3[SP];

#pragma unroll
    for (int j = 0; j < SP; j++) {
        float sm[2][4];                 // [stream lo/hi][k=0..3]
#pragma unroll
        for (int t = 0; t < 2; t++) {   // stream 2j+t
            int ns = n0 + 2 * (2 * j + t);
            float acc[4] = {0.f, 0.f, 0.f, 0.f};
#pragma unroll
            for (int u = 0; u < 2; u++) {   // the 2 n in this merged stream
                int n = ns + u;
                float2 d = s_dta[n];
                float ex = expf(d.x * lf);
                float s, c; sincosf(d.y * lf, &s, &c);
                float er = ex * c, ei = ex * s;
                float2 cm = s_cm[n];
                float zr = cm.x * er - cm.y * ei;
                float zi = cm.x * ei + cm.y * er;
                float2 w = s_w32[n];
#pragma unroll
                for (int k = 0; k < 4; k++) {
                    acc[k] += zr;
                    float tr = zr * w.x - zi * w.y;
                    float ti = zr * w.y + zi * w.x;
                    zr = tr; zi = ti;
                }
            }
#pragma unroll
            for (int k = 0; k < 4; k++) sm[t][k] = acc[k];
        }
        S0[j] = pack2(sm[0][0], sm[1][0]);
        S1[j] = pack2(sm[0][1], sm[1][1]);
        S2[j] = pack2(sm[0][2], sm[1][2]);
        S3[j] = pack2(sm[0][3], sm[1][3]);

        float4 ca = s_c4[(n0 >> 1) + 2 * j];
        float4 cb = s_c4[(n0 >> 1) + 2 * j + 1];
        C0[j] = pack2(ca.x, cb.x);
        C1[j] = pack2(ca.y, cb.y);
        C2[j] = pack2(ca.z, cb.z);
        C3[j] = pack2(ca.w, cb.w);
    }

    float* orow = out + (size_t)h * L;

#pragma unroll 1
    for (int ch = 0; ch < CHUNKS; ch++) {
        if (ch) __syncthreads();            // buffer reusable

        u64* s_slot = &s_part[0][wid][lane];
#pragma unroll 1
        for (int k4 = 0; k4 < CHUNK_K; k4 += 4) {
            // 4 k-steps with static state rotation
#pragma unroll
            for (int kk = 0; kk < 4; kk++) {
                u64 a0, a1;
                // accumulate current oldest state (this k's output) and step
                if (kk == 0) {
                    a0 = add2(S0[0], S0[1]); a1 = add2(S0[2], S0[3]);
#pragma unroll
                    for (int j = 0; j < SP; j++)
                        S0[j] = fma2(C3[j], S3[j], fma2(C2[j], S2[j],
                                 fma2(C1[j], S1[j], mul2(C0[j], S0[j]))));
                } else if (kk == 1) {
                    a0 = add2(S1[0], S1[1]); a1 = add2(S1[2], S1[3]);
#pragma unroll
                    for (int j = 0; j < SP; j++)
                        S1[j] = fma2(C3[j], S0[j], fma2(C2[j], S3[j],
                                 fma2(C1[j], S2[j], mul2(C0[j], S1[j]))));
                } else if (kk == 2) {
                    a0 = add2(S2[0], S2[1]); a1 = add2(S2[2], S2[3]);
#pragma unroll
                    for (int j = 0; j < SP; j++)
                        S2[j] = fma2(C3[j], S1[j], fma2(C2[j], S0[j],
                                 fma2(C1[j], S3[j], mul2(C0[j], S2[j]))));
                } else {
                    a0 = add2(S3[0], S3[1]); a1 = add2(S3[2], S3[3]);
#pragma unroll
                    for (int j = 0; j < SP; j++)
                        S3[j] = fma2(C3[j], S2[j], fma2(C2[j], S1[j],
                                 fma2(C1[j], S0[j], mul2(C0[j], S3[j]))));
                }
                s_slot[(size_t)(k4 + kk) * (WARPS * 32)] = add2(a0, a1);
            }
        }
        __syncthreads();

        // ---- cross-warp reduction: warp w handles k = w + 4i ----
#pragma unroll
        for (int i = 0; i < CHUNK_K / WARPS; i++) {
            int k = wid + WARPS * i;
            float sum = 0.0f;
#pragma unroll
            for (int w = 0; w < WARPS; w++) {
                float lo, hi;
                unpack2(s_part[k][w][lane], lo, hi);
                sum += lo + hi;
            }
            orow[(size_t)(ch * CHUNK_K + k) * 32 + lane] = sum;
        }
    }
}

extern "C" void kernel_launch(void* const* d_in, const int* in_sizes, int n_in,
                              void* d_out, int out_size)
{
    const float* log_dt = (const float*)d_in[0];
    const float* C      = (const float*)d_in[1];
    const float* A      = (const float*)d_in[2];
    // d_in[3] = input_length scalar; L derived from out_size.

    int H = in_sizes[0];          // 1024
    int L = out_size / H;         // 2048

    s4d_fused<<<H, 128>>>(log_dt, C, A, (float*)d_out, L);
}